// round 9
// baseline (speedup 1.0000x reference)
#include <cuda_runtime.h>
#include <cuda_bf16.h>
#include <math.h>

#define NCTA 32
#define NTHR 256
#define TSTEPS 512
#define NL 20
#define BUFSZ (2046 * 1024)

// ---------------- device globals (no allocation allowed) ----------------
__device__ __align__(16) float g_buf[BUFSZ];   // dilation buffers [layer/slot][k][b]
__device__ float g_res[1024];                  // res     [k][b]
__device__ float g_h[1024];                    // h       [k][b]
__device__ float g_skip[1024];                 // relu(skip) [k][b]
__device__ float g_s[1024];                    // relu(s) [k][b]
__device__ float g_logits[2048];               // logits  [q][b]
__device__ unsigned g_cnt;
__device__ unsigned g_gen;

__constant__ int c_off[NL] = {0,1,3,7,15,31,63,127,255,511,
                              1023,1024,1026,1030,1038,1054,1086,1150,1278,1534};

__global__ void wn_init_kernel() {
    int i = blockIdx.x * blockDim.x + threadIdx.x;
    if (i == 0) { g_cnt = 0u; g_gen = 0u; }
    float4 z = make_float4(0.f, 0.f, 0.f, 0.f);
    float4* p = (float4*)g_buf;
    int n4 = BUFSZ / 4;
    for (int j = i; j < n4; j += gridDim.x * blockDim.x) p[j] = z;
}

// Monotonic global barrier over NCTA co-resident CTAs. target = barrier ordinal (1-based).
__device__ __forceinline__ void gbar(unsigned target) {
    __threadfence();          // make this thread's global stores visible device-wide
    __syncthreads();          // order all block threads' stores before the arrive
    if (threadIdx.x == 0) {
        unsigned old = atomicAdd(&g_cnt, 1u);
        if (old == target * NCTA - 1u) {
            atomicAdd(&g_gen, 1u);
        } else {
            volatile unsigned* vg = &g_gen;
            while (*vg < target) { }
        }
        __threadfence();
    }
    __syncthreads();
}

__global__ void __launch_bounds__(NTHR, 1) wn_kernel(
    const float* __restrict__ enc,       // (8,64,8)
    const float* __restrict__ first_w,   // (128,1,2)
    const float* __restrict__ first_b,   // (128)
    const float* __restrict__ causal_w,  // (20,256,128,2)
    const float* __restrict__ causal_b,  // (20,256)
    const float* __restrict__ cond_w,    // (20,256,64)
    const float* __restrict__ cond_b,    // (20,256)
    const float* __restrict__ res_w,     // (20,128,128)
    const float* __restrict__ res_b,     // (20,128)
    const float* __restrict__ skip_w,    // (20,128,128)
    const float* __restrict__ skip_b,    // (20,128)
    const float* __restrict__ skipc_w,   // (128,128)
    const float* __restrict__ skipc_b,   // (128)
    const float* __restrict__ fc_w,      // (128,128)
    const float* __restrict__ fc_b,      // (128)
    const float* __restrict__ condf_w,   // (128,64)
    const float* __restrict__ condf_b,   // (128)
    const float* __restrict__ logits_w,  // (256,128)
    const float* __restrict__ logits_b,  // (256)
    float* __restrict__ out, int logits_base, int write_samples, int write_logits)
{
    __shared__ float sRes[1024];                 // res  [k][b]
    __shared__ float sPrev[1024];                // prev [k][b]
    __shared__ float sH[1024];                   // h / rskip / rs  [k][b]
    __shared__ float sC[512];                    // c [m][b]
    __shared__ __align__(16) float sWz[8 * 264]; // causal slice rows (interleaved w0,w1)
    __shared__ __align__(16) float sWc[8 * 68];  // cond slice rows
    __shared__ float sPA[256];
    __shared__ float sPB[256];
    __shared__ float sZ[64];
    __shared__ float sSkip[32];                  // skip accumulator slice [r4][b]
    __shared__ float sX[8], sPx[8];
    __shared__ int   sSmp[8];
    __shared__ float sAV[256];
    __shared__ int   sAI[256];

    const int tid = threadIdx.x;
    const int cta = blockIdx.x;
    const int q4 = tid >> 6;            // 0..3  (K quarter of 32)
    const int r8 = (tid >> 3) & 7;      // 0..7  (row-in-8-slice)
    const int q8 = tid >> 5;            // 0..7  (K eighth of 16)
    const int r4 = (tid >> 3) & 3;      // 0..3  (row-in-4-slice)
    const int b  = tid & 7;             // batch
    const int hb = cta * 4;             // h / res / skip / s row base
    const int lb = cta * 8;             // logits row base
    unsigned nb = 0;

    if (tid < 8) { sPx[tid] = 0.f; sSmp[tid] = 128; }
    __syncthreads();

    for (int t = 0; t < TSTEPS; t++) {
        // ---- conditioning vector (reload every 64 steps): c[m][b] ----
        if ((t & 63) == 0) {
            int te = t >> 6;
            for (int i = tid; i < 512; i += NTHR) {
                int m = i >> 3, bb = i & 7;
                sC[i] = __ldg(&enc[bb * 512 + m * 8 + te]);
            }
        }
        if (tid < 8) sX[tid] = (float)sSmp[tid] * (1.f / 255.f) - 0.5f;
        __syncthreads();

        // ---- res0 = prev_x * fw0 + x * fw1 + fb  (replicated full) ----
        for (int i = tid; i < 1024; i += NTHR) {
            int k = i >> 3, bb = i & 7;
            sRes[i] = sPx[bb] * __ldg(&first_w[2 * k])
                    + sX[bb]  * __ldg(&first_w[2 * k + 1])
                    + __ldg(&first_b[k]);
        }
        __syncthreads();
        if (tid < 8) sPx[tid] = sX[tid];  // buf_first update (all reads done)

        // ---- skip init slice: res0 @ skipc_w.T + skipc_b ----
        {
            int row = hb + r4;
            float acc = 0.f;
            #pragma unroll
            for (int kk = 0; kk < 16; kk++) {
                int k = q8 * 16 + kk;
                acc = fmaf(sRes[k * 8 + b], __ldg(&skipc_w[row * 128 + k]), acc);
            }
            sPA[q8 * 32 + r4 * 8 + b] = acc;
        }
        __syncthreads();
        if (tid < 32) {
            int row = hb + (tid >> 3);
            float v = __ldg(&skipc_b[row]);
            #pragma unroll
            for (int qq = 0; qq < 8; qq++) v += sPA[qq * 32 + tid];
            sSkip[tid] = v;
        }
        __syncthreads();

        // =================== layers ===================
        for (int l = 0; l < NL; l++) {
            const int d = 1 << (l % 10);
            const int slot = t & (d - 1);
            float* bufL = g_buf + (size_t)(c_off[l] + slot) * 1024;

            // ---- phase Z ----
            for (int i = tid; i < 1024; i += NTHR) sPrev[i] = __ldcg(&bufL[i]);
            if (l > 0)
                for (int i = tid; i < 1024; i += NTHR) sRes[i] = __ldcg(&g_res[i]);
            {
                const float* cw = causal_w + (size_t)l * 256 * 256;
                for (int i = tid; i < 512; i += NTHR) {          // 512 float4
                    int rr = i >> 6, j = i & 63;
                    int zr = (rr < 4) ? (hb + rr) : (128 + hb + rr - 4);
                    ((float4*)&sWz[rr * 264])[j] = __ldg((const float4*)&cw[zr * 256] + j);
                }
                const float* cdw = cond_w + (size_t)l * 256 * 64;
                for (int i = tid; i < 128; i += NTHR) {          // 128 float4
                    int rr = i >> 4, j = i & 15;
                    int zr = (rr < 4) ? (hb + rr) : (128 + hb + rr - 4);
                    ((float4*)&sWc[rr * 68])[j] = __ldg((const float4*)&cdw[zr * 64] + j);
                }
            }
            __syncthreads();
            {
                float acc = 0.f;
                #pragma unroll
                for (int kk = 0; kk < 32; kk++) {
                    int k = q4 * 32 + kk;
                    float w0 = sWz[r8 * 264 + 2 * k];
                    float w1 = sWz[r8 * 264 + 2 * k + 1];
                    acc = fmaf(sPrev[k * 8 + b], w0, acc);
                    acc = fmaf(sRes[k * 8 + b],  w1, acc);
                }
                #pragma unroll
                for (int mm = 0; mm < 16; mm++) {
                    int m = q4 * 16 + mm;
                    acc = fmaf(sC[m * 8 + b], sWc[r8 * 68 + m], acc);
                }
                sPA[tid] = acc;   // == q4*64 + r8*8 + b
            }
            __syncthreads();
            if (tid < 64) {
                int rr = tid >> 3;
                int zr = (rr < 4) ? (hb + rr) : (128 + hb + rr - 4);
                sZ[tid] = sPA[tid] + sPA[64 + tid] + sPA[128 + tid] + sPA[192 + tid]
                        + __ldg(&causal_b[l * 256 + zr]) + __ldg(&cond_b[l * 256 + zr]);
            }
            __syncthreads();
            if (tid < 32) {
                float g = sZ[tid];
                float o = sZ[32 + tid];
                float h = (1.f / (1.f + expf(-g))) * tanhf(o);
                __stcg(&g_h[(hb + (tid >> 3)) * 8 + (tid & 7)], h);
            }
            gbar(++nb);

            // ---- phase 2 ----
            for (int i = tid; i < 1024; i += NTHR) sH[i] = __ldcg(&g_h[i]);
            if (tid < 32) {   // dilation buffer write of res_l slice (prev reads done)
                int idx = (hb + (tid >> 3)) * 8 + (tid & 7);
                __stcg(&bufL[idx], sRes[idx]);
            }
            __syncthreads();
            {
                int row = hb + r4;
                const float* rw = res_w  + (size_t)l * 128 * 128 + row * 128;
                const float* sw = skip_w + (size_t)l * 128 * 128 + row * 128;
                float ar = 0.f, as = 0.f;
                #pragma unroll
                for (int kk = 0; kk < 16; kk++) {
                    int k = q8 * 16 + kk;
                    float hv = sH[k * 8 + b];
                    ar = fmaf(hv, __ldg(&rw[k]), ar);
                    as = fmaf(hv, __ldg(&sw[k]), as);
                }
                sPA[q8 * 32 + r4 * 8 + b] = ar;
                sPB[q8 * 32 + r4 * 8 + b] = as;
            }
            __syncthreads();
            if (tid < 32) {
                int row = hb + (tid >> 3);
                float vr = __ldg(&res_b[l * 128 + row]);
                float vs = __ldg(&skip_b[l * 128 + row]);
                #pragma unroll
                for (int qq = 0; qq < 8; qq++) {
                    vr += sPA[qq * 32 + tid];
                    vs += sPB[qq * 32 + tid];
                }
                sSkip[tid] += vs;
                if (l < NL - 1) {
                    vr += sRes[row * 8 + (tid & 7)];
                    __stcg(&g_res[row * 8 + (tid & 7)], vr);
                }
            }
            if (l < NL - 1) gbar(++nb);
            else            __syncthreads();
        }

        // =================== tail ===================
        if (tid < 32) {
            __stcg(&g_skip[(hb + (tid >> 3)) * 8 + (tid & 7)], fmaxf(sSkip[tid], 0.f));
        }
        gbar(++nb);   // T1
        for (int i = tid; i < 1024; i += NTHR) sH[i] = __ldcg(&g_skip[i]);
        __syncthreads();
        {
            int row = hb + r4;
            float acc = 0.f;
            #pragma unroll
            for (int kk = 0; kk < 16; kk++) {
                int k = q8 * 16 + kk;
                acc = fmaf(sH[k * 8 + b], __ldg(&fc_w[row * 128 + k]), acc);
            }
            #pragma unroll
            for (int mm = 0; mm < 8; mm++) {
                int m = q8 * 8 + mm;
                acc = fmaf(sC[m * 8 + b], __ldg(&condf_w[row * 64 + m]), acc);
            }
            sPA[q8 * 32 + r4 * 8 + b] = acc;
        }
        __syncthreads();
        if (tid < 32) {
            int row = hb + (tid >> 3);
            float v = __ldg(&fc_b[row]) + __ldg(&condf_b[row]);
            #pragma unroll
            for (int qq = 0; qq < 8; qq++) v += sPA[qq * 32 + tid];
            __stcg(&g_s[row * 8 + (tid & 7)], fmaxf(v, 0.f));
        }
        gbar(++nb);   // T2
        for (int i = tid; i < 1024; i += NTHR) sH[i] = __ldcg(&g_s[i]);
        __syncthreads();
        {
            int row = lb + r8;
            float acc = 0.f;
            #pragma unroll
            for (int kk = 0; kk < 32; kk++) {
                int k = q4 * 32 + kk;
                acc = fmaf(sH[k * 8 + b], __ldg(&logits_w[row * 128 + k]), acc);
            }
            sPA[tid] = acc;
        }
        __syncthreads();
        if (tid < 64) {
            int row = lb + (tid >> 3), bb = tid & 7;
            float v = sPA[tid] + sPA[64 + tid] + sPA[128 + tid] + sPA[192 + tid]
                    + __ldg(&logits_b[row]);
            __stcg(&g_logits[row * 8 + bb], v);
            if (write_logits) out[logits_base + t * 2048 + bb * 256 + row] = v;
        }
        gbar(++nb);   // T3
        // ---- replicated argmax (first-index tie-break) ----
        {
            int bb = tid & 7, chunk = tid >> 3;
            float bv = -1e30f; int bi = 0;
            #pragma unroll
            for (int j = 0; j < 8; j++) {
                int qrow = chunk * 8 + j;
                float v = __ldcg(&g_logits[qrow * 8 + bb]);
                if (v > bv) { bv = v; bi = qrow; }
            }
            sAV[tid] = bv; sAI[tid] = bi;
        }
        __syncthreads();
        if (tid < 8) {
            float bv = sAV[tid]; int bi = sAI[tid];
            for (int chunk = 1; chunk < 32; chunk++) {
                float v = sAV[chunk * 8 + tid];
                if (v > bv) { bv = v; bi = sAI[chunk * 8 + tid]; }
            }
            sSmp[tid] = bi;
            if (write_samples && cta == 0) out[t * 8 + tid] = (float)bi;
        }
        __syncthreads();
    }
}

extern "C" void kernel_launch(void* const* d_in, const int* in_sizes, int n_in,
                              void* d_out, int out_size) {
    wn_init_kernel<<<64, 256>>>();
    int wl = 0, ws = 0, lbase = 0;
    if (out_size >= 512 * 8 * 256) {
        wl = 1;
        lbase = out_size - 512 * 8 * 256;   // samples (if present) precede logits
        ws = (lbase >= 512 * 8) ? 1 : 0;
    } else if (out_size >= 512 * 8) {
        ws = 1;
    }
    wn_kernel<<<NCTA, NTHR>>>(
        (const float*)d_in[0],  (const float*)d_in[1],  (const float*)d_in[2],
        (const float*)d_in[3],  (const float*)d_in[4],  (const float*)d_in[5],
        (const float*)d_in[6],  (const float*)d_in[7],  (const float*)d_in[8],
        (const float*)d_in[9],  (const float*)d_in[10], (const float*)d_in[11],
        (const float*)d_in[12], (const float*)d_in[13], (const float*)d_in[14],
        (const float*)d_in[15], (const float*)d_in[16], (const float*)d_in[17],
        (const float*)d_in[18],
        (float*)d_out, lbase, ws, wl);
}

// round 12
// speedup vs baseline: 1.5567x; 1.5567x over previous
#include <cuda_runtime.h>
#include <cuda_bf16.h>
#include <math.h>

#define NCTA 32
#define NTHR 256
#define TSTEPS 512
#define NL 20
#define BUFSZ (2046 * 1024)

// ---------------- device globals (no allocation allowed) ----------------
__device__ __align__(16) float g_buf[BUFSZ];   // dilation buffers, slot = [b][k] (8x128)
__device__ __align__(16) float g_res[1024];    // res        [b][k]
__device__ __align__(16) float g_h[1024];      // h          [b][k]
__device__ __align__(16) float g_skip[1024];   // relu(skip) [b][k]
__device__ __align__(16) float g_s[1024];      // relu(s)    [b][k]
__device__ __align__(16) float g_logits[2048]; // logits     [b][q]
__device__ unsigned g_cnt;
__device__ unsigned g_gen;

__constant__ int c_off[NL] = {0,1,3,7,15,31,63,127,255,511,
                              1023,1024,1026,1030,1038,1054,1086,1150,1278,1534};

__global__ void wn_init_kernel() {
    int i = blockIdx.x * blockDim.x + threadIdx.x;
    if (i == 0) { g_cnt = 0u; g_gen = 0u; }
    float4 z = make_float4(0.f, 0.f, 0.f, 0.f);
    float4* p = (float4*)g_buf;
    int n4 = BUFSZ / 4;
    for (int j = i; j < n4; j += gridDim.x * blockDim.x) p[j] = z;
}

// ---- cp.async helpers ----
__device__ __forceinline__ void cpa16(void* s, const void* g) {
    unsigned sa = (unsigned)__cvta_generic_to_shared(s);
    asm volatile("cp.async.cg.shared.global [%0], [%1], 16;" :: "r"(sa), "l"(g) : "memory");
}
__device__ __forceinline__ void cpcommit() { asm volatile("cp.async.commit_group;" ::: "memory"); }
__device__ __forceinline__ void cpwait0()  { asm volatile("cp.async.wait_group 0;" ::: "memory"); }
__device__ __forceinline__ void cpwait1()  { asm volatile("cp.async.wait_group 1;" ::: "memory"); }

// Monotonic global barrier, acquire/release (no per-thread membars).
__device__ __forceinline__ void gbar(unsigned target) {
    __syncthreads();
    if (threadIdx.x == 0) {
        unsigned old;
        asm volatile("atom.add.acq_rel.gpu.u32 %0, [%1], 1;"
                     : "=r"(old) : "l"(&g_cnt) : "memory");
        if (old == target * NCTA - 1u) {
            asm volatile("red.add.release.gpu.u32 [%0], 1;" :: "l"(&g_gen) : "memory");
        } else {
            unsigned g;
            do {
                asm volatile("ld.acquire.gpu.u32 %0, [%1];" : "=r"(g) : "l"(&g_gen) : "memory");
            } while (g < target);
        }
    }
    __syncthreads();
}

__device__ __forceinline__ float dot4(float4 a, float4 w) {
    return a.x*w.x + a.y*w.y + a.z*w.z + a.w*w.w;
}

__global__ void __launch_bounds__(NTHR, 1) wn_kernel(
    const float* __restrict__ enc,       // (8,64,8)
    const float* __restrict__ first_w,   // (128,1,2)
    const float* __restrict__ first_b,   // (128)
    const float* __restrict__ causal_w,  // (20,256,128,2)
    const float* __restrict__ causal_b,  // (20,256)
    const float* __restrict__ cond_w,    // (20,256,64)
    const float* __restrict__ cond_b,    // (20,256)
    const float* __restrict__ res_w,     // (20,128,128)
    const float* __restrict__ res_b,     // (20,128)
    const float* __restrict__ skip_w,    // (20,128,128)
    const float* __restrict__ skip_b,    // (20,128)
    const float* __restrict__ skipc_w,   // (128,128)
    const float* __restrict__ skipc_b,   // (128)
    const float* __restrict__ fc_w,      // (128,128)
    const float* __restrict__ fc_b,      // (128)
    const float* __restrict__ condf_w,   // (128,64)
    const float* __restrict__ condf_b,   // (128)
    const float* __restrict__ logits_w,  // (256,128)
    const float* __restrict__ logits_b,  // (256)
    float* __restrict__ out, int logits_base, int write_samples, int write_logits)
{
    // activations [b][k], stride 132; weights row-padded (strides keep 16B align + bank spread)
    __shared__ __align__(16) float sPrev[8 * 132];
    __shared__ __align__(16) float sRes [8 * 132];
    __shared__ __align__(16) float sH   [8 * 132];
    __shared__ __align__(16) float sC   [8 * 68];    // c [b][m]
    __shared__ __align__(16) float sWz  [8 * 264];   // causal slice (w0,w1 interleaved over k)
    __shared__ __align__(16) float sWc  [8 * 68];    // cond slice
    __shared__ __align__(16) float sWrs [8 * 132];   // res rows 0-3, skip rows 4-7
    __shared__ __align__(16) float sSkc [4 * 132];   // persistent: skipc slice
    __shared__ __align__(16) float sFc  [4 * 132];   // persistent: fc slice
    __shared__ __align__(16) float sCf  [4 * 68];    // persistent: condf slice
    __shared__ __align__(16) float sLg  [8 * 132];   // persistent: logits slice
    __shared__ __align__(16) float sFw[256];
    __shared__ __align__(16) float sFb[128];
    __shared__ __align__(16) float sBz[2][16];       // DOUBLE-BUFFERED z biases (parity = l&1)
    __shared__ __align__(16) float sBrs[8];          // res_b, skip_b (4 each)
    __shared__ float sSkcB[4], sFcB[4], sLgB[8];
    __shared__ float sPA[256];
    __shared__ float sPB[256];
    __shared__ float sSkip[32];
    __shared__ float sX[8], sPx[8];
    __shared__ int   sSmp[8];
    __shared__ float sAV[256];
    __shared__ int   sAI[256];

    const int tid = threadIdx.x;
    const int cta = blockIdx.x;
    const int q4 = tid >> 6;            // 0..3  K-quarter(32)
    const int r8 = (tid >> 3) & 7;      // 0..7
    const int q8 = tid >> 5;            // 0..7  K-eighth(16)
    const int r4 = (tid >> 3) & 3;      // 0..3
    const int b  = tid & 7;
    const int hb = cta * 4;             // h/res/skip/s row base
    const int lb = cta * 8;             // logits row base
    unsigned nb = 0;

    // ---------- persistent staging (once) ----------
    for (int i = tid; i < 512; i += NTHR) {
        int r = i >> 7, k = i & 127;
        sSkc[r * 132 + k] = __ldg(&skipc_w[(hb + r) * 128 + k]);
        sFc [r * 132 + k] = __ldg(&fc_w   [(hb + r) * 128 + k]);
    }
    for (int i = tid; i < 256; i += NTHR) {
        int r = i >> 6, m = i & 63;
        sCf[r * 68 + m] = __ldg(&condf_w[(hb + r) * 64 + m]);
        sFw[i] = __ldg(&first_w[i]);
    }
    for (int i = tid; i < 1024; i += NTHR) {
        int r = i >> 7, k = i & 127;
        sLg[r * 132 + k] = __ldg(&logits_w[(lb + r) * 128 + k]);
    }
    for (int i = tid; i < 128; i += NTHR) sFb[i] = __ldg(&first_b[i]);
    if (tid < 4) {
        sSkcB[tid] = __ldg(&skipc_b[hb + tid]);
        sFcB[tid]  = __ldg(&fc_b[hb + tid]) + __ldg(&condf_b[hb + tid]);
    }
    if (tid < 8) sLgB[tid] = __ldg(&logits_b[lb + tid]);
    // layer-0 z weights + biases (steady-state comes via cp.async prefetch)
    for (int i = tid; i < 2048; i += NTHR) {
        int rr = i >> 8, j = i & 255;
        int zr = (rr < 4) ? (hb + rr) : (128 + hb + rr - 4);
        sWz[rr * 264 + j] = __ldg(&causal_w[zr * 256 + j]);
    }
    for (int i = tid; i < 512; i += NTHR) {
        int rr = i >> 6, m = i & 63;
        int zr = (rr < 4) ? (hb + rr) : (128 + hb + rr - 4);
        sWc[rr * 68 + m] = __ldg(&cond_w[zr * 64 + m]);
    }
    if (tid < 4) {                         // layer 0 biases -> parity 0
        sBz[0][tid]      = __ldg(&causal_b[hb + tid]);
        sBz[0][4 + tid]  = __ldg(&causal_b[128 + hb + tid]);
        sBz[0][8 + tid]  = __ldg(&cond_b[hb + tid]);
        sBz[0][12 + tid] = __ldg(&cond_b[128 + hb + tid]);
    }
    if (tid < 8) { sPx[tid] = 0.f; sSmp[tid] = 128; }
    __syncthreads();

    for (int t = 0; t < TSTEPS; t++) {
        if ((t & 63) == 0) {
            int te = t >> 6;
            for (int i = tid; i < 512; i += NTHR) {
                int bb = i >> 6, m = i & 63;
                sC[bb * 68 + m] = __ldg(&enc[bb * 512 + m * 8 + te]);
            }
        }
        if (tid < 8) sX[tid] = (float)sSmp[tid] * (1.f / 255.f) - 0.5f;
        __syncthreads();

        // =================== layers ===================
        for (int l = 0; l < NL; l++) {
            const int d = 1 << (l % 10);
            const int slot = t & (d - 1);
            const int par = l & 1;
            float* bufL = g_buf + (size_t)(c_off[l] + slot) * 1024;

            // -- group A: prev (+res for l>0) --
            {
                int bp = tid >> 5, j = tid & 31;
                cpa16(&sPrev[bp * 132 + j * 4], bufL + bp * 128 + j * 4);
                if (l > 0) cpa16(&sRes[bp * 132 + j * 4], g_res + bp * 128 + j * 4);
            }
            cpcommit();
            // -- group B: res_w/skip_w slices + biases --
            if (tid < 128) {
                int rr = tid >> 5, j = tid & 31;
                cpa16(&sWrs[rr * 132 + j * 4],
                      res_w + (size_t)l * 16384 + (hb + rr) * 128 + j * 4);
            } else {
                int i2 = tid - 128, rr = i2 >> 5, j = i2 & 31;
                cpa16(&sWrs[(4 + rr) * 132 + j * 4],
                      skip_w + (size_t)l * 16384 + (hb + rr) * 128 + j * 4);
            }
            if (tid == 0) cpa16(&sBrs[0], res_b  + l * 128 + hb);
            if (tid == 1) cpa16(&sBrs[4], skip_b + l * 128 + hb);
            cpcommit();

            if (l == 0) {
                // res0 = prev_x*fw0 + x*fw1 + fb  (replicated, [b][k])
                for (int i = tid; i < 1024; i += NTHR) {
                    int bb = i >> 7, k = i & 127;
                    sRes[bb * 132 + k] = sPx[bb] * sFw[2 * k] + sX[bb] * sFw[2 * k + 1] + sFb[k];
                }
                __syncthreads();
                if (tid < 8) sPx[tid] = sX[tid];
                // skip init slice
                {
                    float acc = 0.f;
                    #pragma unroll
                    for (int g = 0; g < 4; g++) {
                        int k0 = q8 * 16 + g * 4;
                        acc += dot4(*(const float4*)&sRes[b * 132 + k0],
                                    *(const float4*)&sSkc[r4 * 132 + k0]);
                    }
                    sPA[tid] = acc;
                }
                __syncthreads();
                if (tid < 32) {
                    float v = sSkcB[tid >> 3];
                    #pragma unroll
                    for (int qq = 0; qq < 8; qq++) v += sPA[qq * 32 + tid];
                    sSkip[tid] = v;
                }
            }
            cpwait1();          // A done (B may fly)
            __syncthreads();

            // ---- z dot ----
            {
                float acc = 0.f;
                #pragma unroll
                for (int g = 0; g < 8; g++) {
                    int k0 = q4 * 32 + g * 4;
                    float4 pv  = *(const float4*)&sPrev[b * 132 + k0];
                    float4 rv  = *(const float4*)&sRes [b * 132 + k0];
                    float4 w01 = *(const float4*)&sWz[r8 * 264 + 2 * k0];
                    float4 w23 = *(const float4*)&sWz[r8 * 264 + 2 * k0 + 4];
                    acc = fmaf(pv.x, w01.x, acc); acc = fmaf(rv.x, w01.y, acc);
                    acc = fmaf(pv.y, w01.z, acc); acc = fmaf(rv.y, w01.w, acc);
                    acc = fmaf(pv.z, w23.x, acc); acc = fmaf(rv.z, w23.y, acc);
                    acc = fmaf(pv.w, w23.z, acc); acc = fmaf(rv.w, w23.w, acc);
                }
                #pragma unroll
                for (int g = 0; g < 4; g++) {
                    int m0 = q4 * 16 + g * 4;
                    acc += dot4(*(const float4*)&sC [b  * 68 + m0],
                                *(const float4*)&sWc[r8 * 68 + m0]);
                }
                sPA[tid] = acc;
            }
            __syncthreads();

            // -- group C: prefetch next z weights (sWz/sWc free; biases go to OTHER parity) --
            {
                int ln = (l + 1 < NL) ? (l + 1) : 0;
                int pn = par ^ 1;
                const float* cw  = causal_w + (size_t)ln * 65536;
                const float* cdw = cond_w   + (size_t)ln * 16384;
                #pragma unroll
                for (int rep = 0; rep < 2; rep++) {
                    int i2 = tid + rep * 256;
                    int rr = i2 >> 6, j = i2 & 63;
                    int zr = (rr < 4) ? (hb + rr) : (128 + hb + rr - 4);
                    cpa16(&sWz[rr * 264 + j * 4], cw + zr * 256 + j * 4);
                }
                if (tid < 128) {
                    int rr = tid >> 4, j = tid & 15;
                    int zr = (rr < 4) ? (hb + rr) : (128 + hb + rr - 4);
                    cpa16(&sWc[rr * 68 + j * 4], cdw + zr * 64 + j * 4);
                }
                if (tid == 0) cpa16(&sBz[pn][0],  causal_b + ln * 256 + hb);
                if (tid == 1) cpa16(&sBz[pn][4],  causal_b + ln * 256 + 128 + hb);
                if (tid == 2) cpa16(&sBz[pn][8],  cond_b   + ln * 256 + hb);
                if (tid == 3) cpa16(&sBz[pn][12], cond_b   + ln * 256 + 128 + hb);
            }
            cpcommit();

            // fused reduce + gated activation + publish h (reads CURRENT parity biases)
            if (tid < 32) {
                int r = tid >> 3, bb = tid & 7;
                float g = sBz[par][r]     + sBz[par][8 + r];
                float o = sBz[par][4 + r] + sBz[par][12 + r];
                #pragma unroll
                for (int qq = 0; qq < 4; qq++) {
                    g += sPA[qq * 64 + r * 8 + bb];
                    o += sPA[qq * 64 + (4 + r) * 8 + bb];
                }
                float sg = 1.f / (1.f + __expf(-g));
                float a  = fminf(fabsf(o), 15.f);
                float e  = __expf(2.f * a);
                float th = copysignf(__fdividef(e - 1.f, e + 1.f), o);
                __stcg(&g_h[bb * 128 + hb + r], sg * th);
            }
            gbar(++nb);   // h barrier

            // ---- phase 2 ----
            {
                int bp = tid >> 5, j = tid & 31;
                cpa16(&sH[bp * 132 + j * 4], g_h + bp * 128 + j * 4);
            }
            cpcommit();
            if (tid < 32) {  // dilation-buffer write (all prev reads done at barrier)
                int r = tid >> 3, bb = tid & 7;
                __stcg(&bufL[bb * 128 + hb + r], sRes[bb * 132 + hb + r]);
            }
            cpwait0();
            __syncthreads();
            {
                float ar = 0.f, as = 0.f;
                #pragma unroll
                for (int g = 0; g < 4; g++) {
                    int k0 = q8 * 16 + g * 4;
                    float4 hv = *(const float4*)&sH[b * 132 + k0];
                    float4 rw = *(const float4*)&sWrs[r4 * 132 + k0];
                    float4 sw = *(const float4*)&sWrs[(4 + r4) * 132 + k0];
                    ar = fmaf(hv.x, rw.x, ar); ar = fmaf(hv.y, rw.y, ar);
                    ar = fmaf(hv.z, rw.z, ar); ar = fmaf(hv.w, rw.w, ar);
                    as = fmaf(hv.x, sw.x, as); as = fmaf(hv.y, sw.y, as);
                    as = fmaf(hv.z, sw.z, as); as = fmaf(hv.w, sw.w, as);
                }
                sPA[tid] = ar; sPB[tid] = as;
            }
            __syncthreads();
            if (tid < 32) {
                int r = tid >> 3, bb = tid & 7;
                float vr = sBrs[r], vs = sBrs[4 + r];
                #pragma unroll
                for (int qq = 0; qq < 8; qq++) {
                    vr += sPA[qq * 32 + tid];
                    vs += sPB[qq * 32 + tid];
                }
                sSkip[tid] += vs;
                if (l < NL - 1) {
                    vr += sRes[bb * 132 + hb + r];
                    __stcg(&g_res[bb * 128 + hb + r], vr);
                }
            }
            if (l < NL - 1) gbar(++nb);   // res barrier
            else            __syncthreads();
        }

        // =================== tail ===================
        if (tid < 32) {
            int r = tid >> 3, bb = tid & 7;
            __stcg(&g_skip[bb * 128 + hb + r], fmaxf(sSkip[tid], 0.f));
        }
        gbar(++nb);   // T0
        {
            int bp = tid >> 5, j = tid & 31;
            cpa16(&sH[bp * 132 + j * 4], g_skip + bp * 128 + j * 4);
        }
        cpcommit(); cpwait0(); __syncthreads();
        {
            float acc = 0.f;
            #pragma unroll
            for (int g = 0; g < 4; g++) {
                int k0 = q8 * 16 + g * 4;
                acc += dot4(*(const float4*)&sH[b * 132 + k0],
                            *(const float4*)&sFc[r4 * 132 + k0]);
            }
            #pragma unroll
            for (int g = 0; g < 2; g++) {
                int m0 = q8 * 8 + g * 4;
                acc += dot4(*(const float4*)&sC [b  * 68 + m0],
                            *(const float4*)&sCf[r4 * 68 + m0]);
            }
            sPA[tid] = acc;
        }
        __syncthreads();
        if (tid < 32) {
            int r = tid >> 3, bb = tid & 7;
            float v = sFcB[r];
            #pragma unroll
            for (int qq = 0; qq < 8; qq++) v += sPA[qq * 32 + tid];
            __stcg(&g_s[bb * 128 + hb + r], fmaxf(v, 0.f));
        }
        gbar(++nb);   // T1
        {
            int bp = tid >> 5, j = tid & 31;
            cpa16(&sH[bp * 132 + j * 4], g_s + bp * 128 + j * 4);
        }
        cpcommit(); cpwait0(); __syncthreads();
        {
            float acc = 0.f;
            #pragma unroll
            for (int g = 0; g < 8; g++) {
                int k0 = q4 * 32 + g * 4;
                acc += dot4(*(const float4*)&sH[b * 132 + k0],
                            *(const float4*)&sLg[r8 * 132 + k0]);
            }
            sPA[tid] = acc;
        }
        __syncthreads();
        if (tid < 64) {
            int r = tid >> 3, bb = tid & 7;
            float v = sLgB[r] + sPA[tid] + sPA[64 + tid] + sPA[128 + tid] + sPA[192 + tid];
            int row = lb + r;
            __stcg(&g_logits[bb * 256 + row], v);
            if (write_logits) out[logits_base + t * 2048 + bb * 256 + row] = v;
        }
        gbar(++nb);   // T2
        // ---- replicated argmax (first-index tie-break) ----
        {
            int bb = tid & 7, chunk = tid >> 3;
            float bv = -1e30f; int bi = 0;
            #pragma unroll
            for (int j = 0; j < 8; j++) {
                int qrow = chunk * 8 + j;
                float v = __ldcg(&g_logits[bb * 256 + qrow]);
                if (v > bv) { bv = v; bi = qrow; }
            }
            sAV[tid] = bv; sAI[tid] = bi;
        }
        __syncthreads();
        if (tid < 8) {
            float bv = sAV[tid]; int bi = sAI[tid];
            for (int chunk = 1; chunk < 32; chunk++) {
                float v = sAV[chunk * 8 + tid];
                if (v > bv) { bv = v; bi = sAI[chunk * 8 + tid]; }
            }
            sSmp[tid] = bi;
            if (write_samples && cta == 0) out[t * 8 + tid] = (float)bi;
        }
        __syncthreads();
    }
}

extern "C" void kernel_launch(void* const* d_in, const int* in_sizes, int n_in,
                              void* d_out, int out_size) {
    wn_init_kernel<<<64, 256>>>();
    int wl = 0, ws = 0, lbase = 0;
    if (out_size >= 512 * 8 * 256) {
        wl = 1;
        lbase = out_size - 512 * 8 * 256;   // samples (if present) precede logits
        ws = (lbase >= 512 * 8) ? 1 : 0;
    } else if (out_size >= 512 * 8) {
        ws = 1;
    }
    wn_kernel<<<NCTA, NTHR>>>(
        (const float*)d_in[0],  (const float*)d_in[1],  (const float*)d_in[2],
        (const float*)d_in[3],  (const float*)d_in[4],  (const float*)d_in[5],
        (const float*)d_in[6],  (const float*)d_in[7],  (const float*)d_in[8],
        (const float*)d_in[9],  (const float*)d_in[10], (const float*)d_in[11],
        (const float*)d_in[12], (const float*)d_in[13], (const float*)d_in[14],
        (const float*)d_in[15], (const float*)d_in[16], (const float*)d_in[17],
        (const float*)d_in[18],
        (float*)d_out, lbase, ws, wl);
}